// round 13
// baseline (speedup 1.0000x reference)
#include <cuda_runtime.h>
#include <math.h>

#define H     128
#define PPB   64        // paths per block
#define NTH   128       // threads per block (1 warp per SMSP, max ILP per thread)
#define WS    136       // weight row stride (floats)
#define BS    68        // activation buffer row stride (64 paths + 4 pad)

// ---- shared memory layout (floats): total 56584 = 226336 B ----
#define SMEM_FLOATS 56584
#define SMEM_BYTES  (SMEM_FLOATS * 4)

typedef unsigned long long ull;

// packed fp32x2 FMA (Blackwell sm_103a): acc = a*b + acc, two fp32 lanes per 64-bit pair
#define FMA2(acc, a, b) \
    asm("fma.rn.f32x2 %0, %1, %2, %0;" : "+l"(acc) : "l"(a), "l"(b))
#define PACK2(out, lo, hi) \
    asm("mov.b64 %0, {%1, %2};" : "=l"(out) : "f"(lo), "f"(hi))
#define UNPACK2(lo, hi, in) \
    asm("mov.b64 {%0, %1}, %2;" : "=f"(lo), "=f"(hi) : "l"(in))

__device__ __forceinline__ float sigmoidf_(float x) {
    return __fdividef(1.0f, 1.0f + __expf(-x));
}
__device__ __forceinline__ float siluf_(float x) {
    return x * sigmoidf_(x);
}

// Forward GEMM: C[j][p] = act( sum_k A[k][p] * W[k][j] + b[j] )
// 128 threads: 8 p-groups (8 paths = 4 packed f32x2) x 16 j-groups (8 outputs)
// 64 MACs per 64 B of LDS per thread-k: fma pipe and smem crossbar balanced.
template<bool DOSILU>
__device__ __forceinline__ void gemm_fwd(const float* __restrict__ A,
                                         const float* __restrict__ W,
                                         const float* __restrict__ b,
                                         float* __restrict__ C, int tid)
{
    const int pg = tid & 7, jg = tid >> 3;     // jg 0..15
    const int p8 = pg * 8, j8 = jg * 8;
    ull acc[8][4];                              // [jj][pair]
#pragma unroll
    for (int a = 0; a < 8; a++)
#pragma unroll
        for (int c = 0; c < 4; c++) acc[a][c] = 0ULL;

#pragma unroll 4
    for (int k = 0; k < H; k++) {
        ulonglong2 a01 = *(const ulonglong2*)&A[k * BS + p8];
        ulonglong2 a23 = *(const ulonglong2*)&A[k * BS + p8 + 4];
        ull ap[4] = {a01.x, a01.y, a23.x, a23.y};
        float4 w0 = *(const float4*)&W[k * WS + j8];
        float4 w1 = *(const float4*)&W[k * WS + j8 + 4];
        float wv[8] = {w0.x, w0.y, w0.z, w0.w, w1.x, w1.y, w1.z, w1.w};
#pragma unroll
        for (int jj = 0; jj < 8; jj++) {
            ull wp; PACK2(wp, wv[jj], wv[jj]);
#pragma unroll
            for (int q = 0; q < 4; q++)
                FMA2(acc[jj][q], wp, ap[q]);
        }
    }

#pragma unroll
    for (int jj = 0; jj < 8; jj++) {
        float bb = b[j8 + jj];
        float r[8];
#pragma unroll
        for (int q = 0; q < 4; q++)
            UNPACK2(r[2 * q], r[2 * q + 1], acc[jj][q]);
#pragma unroll
        for (int pp = 0; pp < 8; pp++) {
            float z = r[pp] + bb;
            r[pp] = DOSILU ? siluf_(z) : z;
        }
        *(float4*)&C[(j8 + jj) * BS + p8]     = make_float4(r[0], r[1], r[2], r[3]);
        *(float4*)&C[(j8 + jj) * BS + p8 + 4] = make_float4(r[4], r[5], r[6], r[7]);
    }
}

// Backward GEMM + fused epilogue:
//   dh1[p][k] = sum_j Dz[j][p] * Wg[k][j]
//   dz1 = dh1 * silu'(z1(p,k)),  corr partials into corrp[kg][p][d]
// 128 threads: 8 p-groups x 16 k-groups. Each k-group owns STRIDED k-set
// {kg, kg+16, ..., kg+112}: within one LDS inst lanes carry consecutive kg
// (address stride WS=136 -> bank stride 8 -> conflict-free).
__device__ __forceinline__ void gemm_bwd_epi(const float* __restrict__ Dz,
                                             const float* __restrict__ Wg,
                                             const float* __restrict__ gw1s,
                                             const float* __restrict__ gb1s,
                                             const float* __restrict__ ysm,
                                             float* __restrict__ corrp, int tid)
{
    const int pg = tid & 7, kg = tid >> 3;     // kg 0..15
    const int p8 = pg * 8;
    ull acc[8][4];                              // [m][pair], k = kg + 16*m
#pragma unroll
    for (int a = 0; a < 8; a++)
#pragma unroll
        for (int c = 0; c < 4; c++) acc[a][c] = 0ULL;

#pragma unroll 4
    for (int j = 0; j < H; j++) {
        ulonglong2 a01 = *(const ulonglong2*)&Dz[j * BS + p8];
        ulonglong2 a23 = *(const ulonglong2*)&Dz[j * BS + p8 + 4];
        ull ap[4] = {a01.x, a01.y, a23.x, a23.y};
#pragma unroll
        for (int m = 0; m < 8; m++) {
            float w = Wg[(kg + 16 * m) * WS + j];
            ull wp; PACK2(wp, w, w);
#pragma unroll
            for (int q = 0; q < 4; q++)
                FMA2(acc[m][q], wp, ap[q]);
        }
    }

    // epilogue: dz1 = dh1 * silu'(z1), z1 recomputed from y
    float w0[8], w1[8], bb[8];
#pragma unroll
    for (int m = 0; m < 8; m++) {
        int k = kg + 16 * m;
        w0[m] = gw1s[k];
        w1[m] = gw1s[H + k];
        bb[m] = gb1s[k];
    }
    float dh1[8][8];
#pragma unroll
    for (int m = 0; m < 8; m++)
#pragma unroll
        for (int q = 0; q < 4; q++)
            UNPACK2(dh1[m][2 * q], dh1[m][2 * q + 1], acc[m][q]);

#pragma unroll
    for (int pp = 0; pp < 8; pp++) {
        int p = p8 + pp;
        float ya = ysm[p * 2], yb = ysm[p * 2 + 1];
        float c0 = 0.0f, c1 = 0.0f;
#pragma unroll
        for (int m = 0; m < 8; m++) {
            float z1 = fmaf(ya, w0[m], fmaf(yb, w1[m], bb[m]));
            float s  = sigmoidf_(z1);
            float spr = s * (1.0f + z1 * (1.0f - s));
            float dz1 = dh1[m][pp] * spr;
            c0 = fmaf(dz1, w0[m], c0);
            c1 = fmaf(dz1, w1[m], c1);
        }
        corrp[(kg * PPB + p) * 2]     = c0;
        corrp[(kg * PPB + p) * 2 + 1] = c1;
    }
}

extern "C" __global__ void __launch_bounds__(NTH, 1)
sde_milstein_kernel(const float* __restrict__ y0, const float* __restrict__ ts,
                    const float* __restrict__ dW,
                    const float* __restrict__ fw1, const float* __restrict__ fb1,
                    const float* __restrict__ fw2, const float* __restrict__ fb2,
                    const float* __restrict__ fw3, const float* __restrict__ fb3,
                    const float* __restrict__ gw1, const float* __restrict__ gb1,
                    const float* __restrict__ gw2, const float* __restrict__ gb2,
                    const float* __restrict__ gw3, const float* __restrict__ gb3,
                    float* __restrict__ out, int T, int NP)
{
    extern __shared__ float sm[];
    float* fw2s = sm;                      // 17408
    float* gw2s = fw2s + H * WS;           // 17408
    float* buf1 = gw2s + H * WS;           // 8704
    float* buf2 = buf1 + H * BS;           // 8704
    float* corrp = buf2 + H * BS;          // 2048
    float* fw1s = corrp + 16 * PPB * 2;    // 384   [i*128+k]
    float* fb1s = fw1s + 3 * H;            // 128
    float* fb2s = fb1s + H;                // 128
    float* fw3s = fb2s + H;                // 256   [j*2+d]
    float* fb3s = fw3s + H * 2;            // 4
    float* gw1s = fb3s + 4;                // 256   [i*128+k]
    float* gb1s = gw1s + 2 * H;            // 128
    float* gb2s = gb1s + H;                // 128
    float* gw3s = gb2s + H;                // 256   [j*2+d]
    float* gb3s = gw3s + H * 2;            // 4
    float* ysm  = gb3s + 4;                // 128   [p*2+d]
    float* f_sm = ysm + PPB * 2;           // 128
    float* g_sm = f_sm + PPB * 2;          // 128
    float* dw_sm = g_sm + PPB * 2;         // 128
    float* dr_sm = dw_sm + PPB * 2;        // 128

    const int tid = threadIdx.x;
    const int p0g = blockIdx.x * PPB;

    // ---- load weights into shared ----
    for (int i = tid; i < H * H; i += NTH) {
        int k = i >> 7, j = i & 127;
        fw2s[k * WS + j] = fw2[i];
        gw2s[k * WS + j] = gw2[i];
    }
    for (int i = tid; i < 3 * H; i += NTH) fw1s[i] = fw1[i];
    for (int i = tid; i < 2 * H; i += NTH) {
        gw1s[i] = gw1[i];
        fw3s[i] = fw3[i];
        gw3s[i] = gw3[i];
    }
    for (int i = tid; i < H; i += NTH) {
        fb1s[i] = fb1[i]; fb2s[i] = fb2[i];
        gb1s[i] = gb1[i]; gb2s[i] = gb2[i];
    }
    if (tid < 2) { fb3s[tid] = fb3[tid]; gb3s[tid] = gb3[tid]; }

    // ---- init state + write t=0 output ----
    {
        int p = tid >> 1, d = tid & 1;
        float v = y0[(size_t)(p0g) * 2 + tid];
        ysm[tid] = v;
        out[(size_t)(p0g + p) * (size_t)(T * 2) + d] = v;
    }
    __syncthreads();

    const int pA = tid & 63;     // path for elementwise-over-k phases
    const int kA = tid >> 6;     // starting k (0 or 1), step 2

    for (int t = 0; t < T - 1; ++t) {
        float dt = ts[t + 1] - ts[t];
        float sqdt = sqrtf(dt);

        // P1: drift layer1 -> buf1 = silu([y, spread] @ fw1 + fb1), transposed [k][p]
        {
            float ya = ysm[pA * 2], yb = ysm[pA * 2 + 1], yc = ya - yb;
#pragma unroll 4
            for (int k = kA; k < H; k += 2) {
                float z = fb1s[k];
                z = fmaf(ya, fw1s[k], z);
                z = fmaf(yb, fw1s[H + k], z);
                z = fmaf(yc, fw1s[2 * H + k], z);
                buf1[k * BS + pA] = siluf_(z);
            }
        }
        __syncthreads();

        // G1: h2f = silu(h1f @ fw2 + fb2) -> buf2
        gemm_fwd<true>(buf1, fw2s, fb2s, buf2, tid);
        __syncthreads();

        // P3: f = h2f @ fw3 + fb3       (one thread per (p,d))
        {
            int p = tid >> 1, d = tid & 1;
            float a0 = 0.0f, a1 = 0.0f;
#pragma unroll 8
            for (int j = 0; j < H; j += 2) {
                a0 = fmaf(buf2[j * BS + p],       fw3s[j * 2 + d],       a0);
                a1 = fmaf(buf2[(j + 1) * BS + p], fw3s[(j + 1) * 2 + d], a1);
            }
            f_sm[tid] = a0 + a1 + fb3s[d];
        }
        // P4: diffusion layer1 -> buf1 (disjoint buffer, no sync needed vs P3)
        {
            float ya = ysm[pA * 2], yb = ysm[pA * 2 + 1];
#pragma unroll 4
            for (int k = kA; k < H; k += 2) {
                float z = fmaf(ya, gw1s[k], fmaf(yb, gw1s[H + k], gb1s[k]));
                buf1[k * BS + pA] = siluf_(z);
            }
        }
        __syncthreads();

        // G2: z2g = h1g @ gw2 + gb2 (PRE-activation kept for backward) -> buf2
        gemm_fwd<false>(buf1, gw2s, gb2s, buf2, tid);
        __syncthreads();

        // P6: g = clip(softplus(raw)), Milstein cotangent draw (dual chains)
        {
            int p = tid >> 1, d = tid & 1;
            float a0 = 0.0f, a1 = 0.0f;
#pragma unroll 4
            for (int j = 0; j < H; j += 2) {
                a0 = fmaf(siluf_(buf2[j * BS + p]),       gw3s[j * 2 + d],       a0);
                a1 = fmaf(siluf_(buf2[(j + 1) * BS + p]), gw3s[(j + 1) * 2 + d], a1);
            }
            float raw = a0 + a1 + gb3s[d];
            float e  = __expf(raw);
            float sp = (raw > 15.0f) ? raw : log1pf(e);
            float g  = fminf(fmaxf(sp, 1e-4f), 5.0f);
            float dwv = dW[((size_t)t * (size_t)NP + (p0g + p)) * 2 + d] * sqdt;
            float v   = 0.5f * (dwv * dwv - dt);
            float sig = __fdividef(e, 1.0f + e);              // sigmoid(raw)
            float m   = (sp > 1e-4f && sp < 5.0f) ? 1.0f : 0.0f;
            g_sm[tid]  = g;
            dw_sm[tid] = dwv;
            dr_sm[tid] = v * g * sig * m;
        }
        __syncthreads();

        // P7: dz2 = (draw @ gw3^T) * silu'(z2g) -> buf1
        {
            float r0 = dr_sm[pA * 2], r1 = dr_sm[pA * 2 + 1];
#pragma unroll 4
            for (int k = kA; k < H; k += 2) {
                float z = buf2[k * BS + pA];
                float s = sigmoidf_(z);
                float spr = s * (1.0f + z * (1.0f - s));
                float dh2 = fmaf(r0, gw3s[k * 2], r1 * gw3s[k * 2 + 1]);
                buf1[k * BS + pA] = dh2 * spr;
            }
        }
        __syncthreads();

        // G3: dh1 = dz2 @ gw2^T, fused dz1 + corr partials -> corrp
        gemm_bwd_epi(buf1, gw2s, gw1s, gb1s, ysm, corrp, tid);
        __syncthreads();

        // P9: reduce corr, Milstein update, write output
        {
            int p = tid >> 1, d = tid & 1;
            float c0 = 0.0f, c1 = 0.0f;
#pragma unroll
            for (int kg = 0; kg < 16; kg += 2) {
                c0 += corrp[(kg * PPB + p) * 2 + d];
                c1 += corrp[((kg + 1) * PPB + p) * 2 + d];
            }
            float yn = ysm[tid] + f_sm[tid] * dt + g_sm[tid] * dw_sm[tid] + (c0 + c1);
            ysm[tid] = yn;
            out[(size_t)(p0g + p) * (size_t)(T * 2) + (size_t)(t + 1) * 2 + d] = yn;
        }
        __syncthreads();
    }
}

extern "C" void kernel_launch(void* const* d_in, const int* in_sizes, int n_in,
                              void* d_out, int out_size)
{
    const float* y0  = (const float*)d_in[0];
    const float* ts  = (const float*)d_in[1];
    const float* dW  = (const float*)d_in[2];
    const float* fw1 = (const float*)d_in[3];
    const float* fb1 = (const float*)d_in[4];
    const float* fw2 = (const float*)d_in[5];
    const float* fb2 = (const float*)d_in[6];
    const float* fw3 = (const float*)d_in[7];
    const float* fb3 = (const float*)d_in[8];
    const float* gw1 = (const float*)d_in[9];
    const float* gb1 = (const float*)d_in[10];
    const float* gw2 = (const float*)d_in[11];
    const float* gb2 = (const float*)d_in[12];
    const float* gw3 = (const float*)d_in[13];
    const float* gb3 = (const float*)d_in[14];
    float* out = (float*)d_out;

    int T  = in_sizes[1];          // 512
    int NP = in_sizes[0] / 2;      // 8192
    int nb = NP / PPB;             // 128 blocks

    cudaFuncSetAttribute(sde_milstein_kernel,
                         cudaFuncAttributeMaxDynamicSharedMemorySize, SMEM_BYTES);

    sde_milstein_kernel<<<nb, NTH, SMEM_BYTES>>>(
        y0, ts, dW, fw1, fb1, fw2, fb2, fw3, fb3,
        gw1, gb1, gw2, gb2, gw3, gb3, out, T, NP);
}

// round 14
// speedup vs baseline: 1.2532x; 1.2532x over previous
#include <cuda_runtime.h>
#include <math.h>

#define H     128
#define PPB   64        // paths per block
#define NTH   128       // threads per block (1 warp per SMSP, max ILP per thread)
#define WS    136       // weight row stride (floats)
#define BS    68        // activation buffer row stride (64 paths + 4 pad)

#define SMEM_FLOATS 56584
#define SMEM_BYTES  (SMEM_FLOATS * 4)

typedef unsigned long long ull;

// packed fp32x2 FMA (saves issue slots; fp32 rate unchanged)
#define FMA2(acc, a, b) \
    asm("fma.rn.f32x2 %0, %1, %2, %0;" : "+l"(acc) : "l"(a), "l"(b))
#define PACK2(out, lo, hi) \
    asm("mov.b64 %0, {%1, %2};" : "=l"(out) : "f"(lo), "f"(hi))
#define UNPACK2(lo, hi, in) \
    asm("mov.b64 {%0, %1}, %2;" : "=f"(lo), "=f"(hi) : "l"(in))

// 1-MUFU sigmoid/silu via hardware tanh (sm_75+): sigmoid(x)=0.5*tanh(x/2)+0.5
__device__ __forceinline__ float tanh_(float x) {
    float t; asm("tanh.approx.f32 %0, %1;" : "=f"(t) : "f"(x)); return t;
}
__device__ __forceinline__ float sigmoidf_(float x) {
    return fmaf(0.5f, tanh_(0.5f * x), 0.5f);
}
__device__ __forceinline__ float siluf_(float x) {
    float hx = 0.5f * x;
    return fmaf(hx, tanh_(hx), hx);            // x*sigmoid(x)
}

// Forward GEMM with FUSED 2-wide head:
//   z[j][p] = sum_k A[k][p]*W[k][j] + b[j]
//   head partials: part[jg][p][d] = sum_{j in group} silu(z)*hw[j][d]
//   STORE_PRE: also store z (pre-activation) to Cpre (needed for backward)
// 128 threads: 8 p-groups (8 paths) x 16 j-groups (8 outputs)
template<bool STORE_PRE>
__device__ __forceinline__ void gemm_head(const float* __restrict__ A,
                                          const float* __restrict__ W,
                                          const float* __restrict__ b,
                                          const float* __restrict__ hw,   // [j*2+d]
                                          float* __restrict__ Cpre,
                                          float* __restrict__ part, int tid)
{
    const int pg = tid & 7, jg = tid >> 3;     // jg 0..15
    const int p8 = pg * 8, j8 = jg * 8;
    ull acc[8][4];
#pragma unroll
    for (int a = 0; a < 8; a++)
#pragma unroll
        for (int c = 0; c < 4; c++) acc[a][c] = 0ULL;

#pragma unroll 4
    for (int k = 0; k < H; k++) {
        ulonglong2 a01 = *(const ulonglong2*)&A[k * BS + p8];
        ulonglong2 a23 = *(const ulonglong2*)&A[k * BS + p8 + 4];
        ull ap[4] = {a01.x, a01.y, a23.x, a23.y};
        float4 w0 = *(const float4*)&W[k * WS + j8];
        float4 w1 = *(const float4*)&W[k * WS + j8 + 4];
        float wv[8] = {w0.x, w0.y, w0.z, w0.w, w1.x, w1.y, w1.z, w1.w};
#pragma unroll
        for (int jj = 0; jj < 8; jj++) {
            ull wp; PACK2(wp, wv[jj], wv[jj]);
#pragma unroll
            for (int q = 0; q < 4; q++)
                FMA2(acc[jj][q], wp, ap[q]);
        }
    }

    float hp[16];                               // interleaved [pp*2+d]
#pragma unroll
    for (int i = 0; i < 16; i++) hp[i] = 0.0f;

#pragma unroll
    for (int jj = 0; jj < 8; jj++) {
        int j = j8 + jj;
        float bb = b[j];
        float wh0 = hw[j * 2], wh1 = hw[j * 2 + 1];
        float r[8];
#pragma unroll
        for (int q = 0; q < 4; q++)
            UNPACK2(r[2 * q], r[2 * q + 1], acc[jj][q]);
        float pre[8];
#pragma unroll
        for (int pp = 0; pp < 8; pp++) {
            float z = r[pp] + bb;
            if (STORE_PRE) pre[pp] = z;
            float s = siluf_(z);
            hp[pp * 2]     = fmaf(s, wh0, hp[pp * 2]);
            hp[pp * 2 + 1] = fmaf(s, wh1, hp[pp * 2 + 1]);
        }
        if (STORE_PRE) {
            *(float4*)&Cpre[j * BS + p8]     = make_float4(pre[0], pre[1], pre[2], pre[3]);
            *(float4*)&Cpre[j * BS + p8 + 4] = make_float4(pre[4], pre[5], pre[6], pre[7]);
        }
    }
    // partials: part[jg*128 + p*2 + d], 16 contiguous floats per thread
    float* pb = &part[jg * 128 + p8 * 2];
#pragma unroll
    for (int q = 0; q < 4; q++)
        ((float4*)pb)[q] = make_float4(hp[4 * q], hp[4 * q + 1], hp[4 * q + 2], hp[4 * q + 3]);
}

// Backward GEMM + fused epilogue:
//   dh1[p][k] = sum_j Dz[j][p] * Wg[k][j];  dz1 = dh1 * silu'(z1(p,k))
//   corr partials -> part[kg][p][d]
// Strided k-set {kg, kg+16, ..., kg+112}: conflict-free W column reads.
__device__ __forceinline__ void gemm_bwd_epi(const float* __restrict__ Dz,
                                             const float* __restrict__ Wg,
                                             const float* __restrict__ gw1s,
                                             const float* __restrict__ gb1s,
                                             const float* __restrict__ ysm,
                                             float* __restrict__ part, int tid)
{
    const int pg = tid & 7, kg = tid >> 3;     // kg 0..15
    const int p8 = pg * 8;
    ull acc[8][4];                              // [m][pair], k = kg + 16*m
#pragma unroll
    for (int a = 0; a < 8; a++)
#pragma unroll
        for (int c = 0; c < 4; c++) acc[a][c] = 0ULL;

#pragma unroll 4
    for (int j = 0; j < H; j++) {
        ulonglong2 a01 = *(const ulonglong2*)&Dz[j * BS + p8];
        ulonglong2 a23 = *(const ulonglong2*)&Dz[j * BS + p8 + 4];
        ull ap[4] = {a01.x, a01.y, a23.x, a23.y};
#pragma unroll
        for (int m = 0; m < 8; m++) {
            float w = Wg[(kg + 16 * m) * WS + j];
            ull wp; PACK2(wp, w, w);
#pragma unroll
            for (int q = 0; q < 4; q++)
                FMA2(acc[m][q], wp, ap[q]);
        }
    }

    float w0[8], w1[8], bb[8];
#pragma unroll
    for (int m = 0; m < 8; m++) {
        int k = kg + 16 * m;
        w0[m] = gw1s[k];
        w1[m] = gw1s[H + k];
        bb[m] = gb1s[k];
    }
    float dh1[8][8];
#pragma unroll
    for (int m = 0; m < 8; m++)
#pragma unroll
        for (int q = 0; q < 4; q++)
            UNPACK2(dh1[m][2 * q], dh1[m][2 * q + 1], acc[m][q]);

    float cc[16];
#pragma unroll
    for (int pp = 0; pp < 8; pp++) {
        int p = p8 + pp;
        float ya = ysm[p * 2], yb = ysm[p * 2 + 1];
        float c0 = 0.0f, c1 = 0.0f;
#pragma unroll
        for (int m = 0; m < 8; m++) {
            float z1 = fmaf(ya, w0[m], fmaf(yb, w1[m], bb[m]));
            float s  = sigmoidf_(z1);
            float spr = s * (1.0f + z1 * (1.0f - s));
            float dz1 = dh1[m][pp] * spr;
            c0 = fmaf(dz1, w0[m], c0);
            c1 = fmaf(dz1, w1[m], c1);
        }
        cc[pp * 2] = c0; cc[pp * 2 + 1] = c1;
    }
    float* pb = &part[kg * 128 + p8 * 2];
#pragma unroll
    for (int q = 0; q < 4; q++)
        ((float4*)pb)[q] = make_float4(cc[4 * q], cc[4 * q + 1], cc[4 * q + 2], cc[4 * q + 3]);
}

extern "C" __global__ void __launch_bounds__(NTH, 1)
sde_milstein_kernel(const float* __restrict__ y0, const float* __restrict__ ts,
                    const float* __restrict__ dW,
                    const float* __restrict__ fw1, const float* __restrict__ fb1,
                    const float* __restrict__ fw2, const float* __restrict__ fb2,
                    const float* __restrict__ fw3, const float* __restrict__ fb3,
                    const float* __restrict__ gw1, const float* __restrict__ gb1,
                    const float* __restrict__ gw2, const float* __restrict__ gb2,
                    const float* __restrict__ gw3, const float* __restrict__ gb3,
                    float* __restrict__ out, int T, int NP)
{
    extern __shared__ float sm[];
    float* fw2s = sm;                      // 17408
    float* gw2s = fw2s + H * WS;           // 17408
    float* buf1 = gw2s + H * WS;           // 8704
    float* buf2 = buf1 + H * BS;           // 8704  (z2g between G2 and P7)
    float* part = buf2 + H * BS;           // 2048  (f-part / raw-part / corr-part, time-disjoint)
    float* fw1s = part + 16 * PPB * 2;     // 384   [i*128+k]
    float* fb1s = fw1s + 3 * H;            // 128
    float* fb2s = fb1s + H;                // 128
    float* fw3s = fb2s + H;                // 256   [j*2+d]
    float* fb3s = fw3s + H * 2;            // 4
    float* gw1s = fb3s + 4;                // 256   [i*128+k]
    float* gb1s = gw1s + 2 * H;            // 128
    float* gb2s = gb1s + H;                // 128
    float* gw3s = gb2s + H;                // 256   [j*2+d]
    float* gb3s = gw3s + H * 2;            // 4
    float* ysm  = gb3s + 4;                // 128   [p*2+d]
    float* f_sm = ysm + PPB * 2;           // 128
    float* g_sm = f_sm + PPB * 2;          // 128
    float* dw_sm = g_sm + PPB * 2;         // 128
    float* dr_sm = dw_sm + PPB * 2;        // 128

    const int tid = threadIdx.x;
    const int p0g = blockIdx.x * PPB;

    // ---- load weights into shared ----
    for (int i = tid; i < H * H; i += NTH) {
        int k = i >> 7, j = i & 127;
        fw2s[k * WS + j] = fw2[i];
        gw2s[k * WS + j] = gw2[i];
    }
    for (int i = tid; i < 3 * H; i += NTH) fw1s[i] = fw1[i];
    for (int i = tid; i < 2 * H; i += NTH) {
        gw1s[i] = gw1[i];
        fw3s[i] = fw3[i];
        gw3s[i] = gw3[i];
    }
    for (int i = tid; i < H; i += NTH) {
        fb1s[i] = fb1[i]; fb2s[i] = fb2[i];
        gb1s[i] = gb1[i]; gb2s[i] = gb2[i];
    }
    if (tid < 2) { fb3s[tid] = fb3[tid]; gb3s[tid] = gb3[tid]; }

    // ---- init state + write t=0 output ----
    {
        int p = tid >> 1, d = tid & 1;
        float v = y0[(size_t)(p0g) * 2 + tid];
        ysm[tid] = v;
        out[(size_t)(p0g + p) * (size_t)(T * 2) + d] = v;
    }
    __syncthreads();

    const int pA = tid & 63;     // path for elementwise-over-k phases
    const int kA = tid >> 6;     // starting k (0 or 1), step 2

    for (int t = 0; t < T - 1; ++t) {
        float dt = ts[t + 1] - ts[t];
        float sqdt = sqrtf(dt);

        // P1: drift layer1 -> buf1 = silu([y, spread] @ fw1 + fb1), transposed [k][p]
        {
            float ya = ysm[pA * 2], yb = ysm[pA * 2 + 1], yc = ya - yb;
#pragma unroll 4
            for (int k = kA; k < H; k += 2) {
                float z = fb1s[k];
                z = fmaf(ya, fw1s[k], z);
                z = fmaf(yb, fw1s[H + k], z);
                z = fmaf(yc, fw1s[2 * H + k], z);
                buf1[k * BS + pA] = siluf_(z);
            }
        }
        __syncthreads();

        // G1: drift L2 + fused f-head -> part (no activation buffer written)
        gemm_head<false>(buf1, fw2s, fb2s, fw3s, (float*)0, part, tid);
        __syncthreads();

        // P4: f-reduce  +  diffusion layer1 -> buf1
        {
            float a = 0.0f;
#pragma unroll
            for (int jg2 = 0; jg2 < 16; jg2++) a += part[jg2 * 128 + tid];
            f_sm[tid] = a + fb3s[tid & 1];

            float ya = ysm[pA * 2], yb = ysm[pA * 2 + 1];
#pragma unroll 4
            for (int k = kA; k < H; k += 2) {
                float z = fmaf(ya, gw1s[k], fmaf(yb, gw1s[H + k], gb1s[k]));
                buf1[k * BS + pA] = siluf_(z);
            }
        }
        __syncthreads();

        // G2: diffusion L2 -> buf2 (pre-act z2g) + fused raw-head -> part
        gemm_head<true>(buf1, gw2s, gb2s, gw3s, buf2, part, tid);
        __syncthreads();

        // P6: reduce raw; g = clip(softplus(raw)); Milstein cotangent draw
        {
            int p = tid >> 1, d = tid & 1;
            float raw = gb3s[d];
#pragma unroll
            for (int jg2 = 0; jg2 < 16; jg2++) raw += part[jg2 * 128 + tid];
            float e  = __expf(raw);
            float sp = (raw > 15.0f) ? raw : log1pf(e);
            float g  = fminf(fmaxf(sp, 1e-4f), 5.0f);
            float dwv = dW[((size_t)t * (size_t)NP + (p0g + p)) * 2 + d] * sqdt;
            float v   = 0.5f * (dwv * dwv - dt);
            float sig = __fdividef(e, 1.0f + e);              // exact sigmoid(raw)
            float m   = (sp > 1e-4f && sp < 5.0f) ? 1.0f : 0.0f;
            g_sm[tid]  = g;
            dw_sm[tid] = dwv;
            dr_sm[tid] = v * g * sig * m;
        }
        __syncthreads();

        // P7: dz2 = (draw @ gw3^T) * silu'(z2g) -> buf1
        {
            float r0 = dr_sm[pA * 2], r1 = dr_sm[pA * 2 + 1];
#pragma unroll 4
            for (int k = kA; k < H; k += 2) {
                float z = buf2[k * BS + pA];
                float s = sigmoidf_(z);
                float spr = s * (1.0f + z * (1.0f - s));
                float dh2 = fmaf(r0, gw3s[k * 2], r1 * gw3s[k * 2 + 1]);
                buf1[k * BS + pA] = dh2 * spr;
            }
        }
        __syncthreads();

        // G3: dh1 = dz2 @ gw2^T, fused dz1 + corr partials -> part
        gemm_bwd_epi(buf1, gw2s, gw1s, gb1s, ysm, part, tid);
        __syncthreads();

        // P9: reduce corr, Milstein update, write output
        {
            int p = tid >> 1, d = tid & 1;
            float c = 0.0f;
#pragma unroll
            for (int kg = 0; kg < 16; kg++) c += part[kg * 128 + tid];
            float yn = ysm[tid] + f_sm[tid] * dt + g_sm[tid] * dw_sm[tid] + c;
            ysm[tid] = yn;
            out[(size_t)(p0g + p) * (size_t)(T * 2) + (size_t)(t + 1) * 2 + d] = yn;
        }
        __syncthreads();
    }
}

extern "C" void kernel_launch(void* const* d_in, const int* in_sizes, int n_in,
                              void* d_out, int out_size)
{
    const float* y0  = (const float*)d_in[0];
    const float* ts  = (const float*)d_in[1];
    const float* dW  = (const float*)d_in[2];
    const float* fw1 = (const float*)d_in[3];
    const float* fb1 = (const float*)d_in[4];
    const float* fw2 = (const float*)d_in[5];
    const float* fb2 = (const float*)d_in[6];
    const float* fw3 = (const float*)d_in[7];
    const float* fb3 = (const float*)d_in[8];
    const float* gw1 = (const float*)d_in[9];
    const float* gb1 = (const float*)d_in[10];
    const float* gw2 = (const float*)d_in[11];
    const float* gb2 = (const float*)d_in[12];
    const float* gw3 = (const float*)d_in[13];
    const float* gb3 = (const float*)d_in[14];
    float* out = (float*)d_out;

    int T  = in_sizes[1];          // 512
    int NP = in_sizes[0] / 2;      // 8192
    int nb = NP / PPB;             // 128 blocks

    cudaFuncSetAttribute(sde_milstein_kernel,
                         cudaFuncAttributeMaxDynamicSharedMemorySize, SMEM_BYTES);

    sde_milstein_kernel<<<nb, NTH, SMEM_BYTES>>>(
        y0, ts, dW, fw1, fb1, fw2, fb2, fw3, fb3,
        gw1, gb1, gw2, gb2, gw3, gb3, out, T, NP);
}

// round 17
// speedup vs baseline: 1.5968x; 1.2742x over previous
#include <cuda_runtime.h>
#include <math.h>

#define H     128
#define PPB   64        // paths per block
#define NTH   256       // threads: 8 warps -> 2 per SMSP; GEMM k-split keeps per-thread tile 8x8
#define WS    136       // weight row stride (floats)
#define BS    68        // activation buffer row stride (64 paths + 4 pad)

#define SMEM_FLOATS 56584
#define SMEM_BYTES  (SMEM_FLOATS * 4)

typedef unsigned long long ull;

// packed fp32x2 FMA (2 fp32 FLOPs per inst, rt 2 -> 2x scalar fp32 throughput)
#define FMA2(acc, a, b) \
    asm("fma.rn.f32x2 %0, %1, %2, %0;" : "+l"(acc) : "l"(a), "l"(b))
#define PACK2(out, lo, hi) \
    asm("mov.b64 %0, {%1, %2};" : "=l"(out) : "f"(lo), "f"(hi))
#define UNPACK2(lo, hi, in) \
    asm("mov.b64 {%0, %1}, %2;" : "=f"(lo), "=f"(hi) : "l"(in))

__device__ __forceinline__ float shflx8(float v) {
    return __shfl_xor_sync(0xffffffffu, v, 8);
}

// 1-MUFU sigmoid/silu via hardware tanh: sigmoid(x)=0.5*tanh(x/2)+0.5
__device__ __forceinline__ float tanh_(float x) {
    float t; asm("tanh.approx.f32 %0, %1;" : "=f"(t) : "f"(x)); return t;
}
__device__ __forceinline__ float sigmoidf_(float x) {
    return fmaf(0.5f, tanh_(0.5f * x), 0.5f);
}
__device__ __forceinline__ float siluf_(float x) {
    float hx = 0.5f * x;
    return fmaf(hx, tanh_(hx), hx);            // x*sigmoid(x)
}

// Forward GEMM with fused 2-wide head, k-split across lane-bit-3 partners.
// Thread (pg, h, jg): 8 paths x 8 outputs, k = h (mod 2). After the mainloop,
// partners exchange via shfl so h owns jj = h*4..h*4+3 full sums.
template<bool STORE_PRE>
__device__ __forceinline__ void gemm_head(const float* __restrict__ A,
                                          const float* __restrict__ W,
                                          const float* __restrict__ b,
                                          const float* __restrict__ hw,   // [j*2+d]
                                          float* __restrict__ Cpre,
                                          float* __restrict__ part, int tid)
{
    const int pg = tid & 7, h = (tid >> 3) & 1, jg = tid >> 4;   // jg 0..15
    const int p8 = pg * 8, j8 = jg * 8;
    ull acc[8][4];
#pragma unroll
    for (int a = 0; a < 8; a++)
#pragma unroll
        for (int c = 0; c < 4; c++) acc[a][c] = 0ULL;

#pragma unroll 4
    for (int kk = 0; kk < H / 2; kk++) {
        int k = 2 * kk + h;
        ulonglong2 a01 = *(const ulonglong2*)&A[k * BS + p8];
        ulonglong2 a23 = *(const ulonglong2*)&A[k * BS + p8 + 4];
        ull ap[4] = {a01.x, a01.y, a23.x, a23.y};
        float4 w0 = *(const float4*)&W[k * WS + j8];
        float4 w1 = *(const float4*)&W[k * WS + j8 + 4];
        float wv[8] = {w0.x, w0.y, w0.z, w0.w, w1.x, w1.y, w1.z, w1.w};
#pragma unroll
        for (int jj = 0; jj < 8; jj++) {
            ull wp; PACK2(wp, wv[jj], wv[jj]);
#pragma unroll
            for (int q = 0; q < 4; q++)
                FMA2(acc[jj][q], wp, ap[q]);
        }
    }

    // cross-h combine: each thread keeps full sums for its owned 4 jj
    float r[4][8];
#pragma unroll
    for (int jj2 = 0; jj2 < 4; jj2++) {
#pragma unroll
        for (int q = 0; q < 4; q++) {
            ull mine = h ? acc[jj2 + 4][q] : acc[jj2][q];
            ull othr = h ? acc[jj2][q]     : acc[jj2 + 4][q];
            float lo, hi;  UNPACK2(lo, hi, mine);
            float plo, phi; UNPACK2(plo, phi, othr);
            r[jj2][2 * q]     = lo + shflx8(plo);
            r[jj2][2 * q + 1] = hi + shflx8(phi);
        }
    }

    float hp[16];
#pragma unroll
    for (int i = 0; i < 16; i++) hp[i] = 0.0f;

#pragma unroll
    for (int jj2 = 0; jj2 < 4; jj2++) {
        int j = j8 + h * 4 + jj2;
        float bb = b[j];
        float wh0 = hw[j * 2], wh1 = hw[j * 2 + 1];
        float pre[8];
#pragma unroll
        for (int pp = 0; pp < 8; pp++) {
            float z = r[jj2][pp] + bb;
            if (STORE_PRE) pre[pp] = z;
            float s = siluf_(z);
            hp[pp * 2]     = fmaf(s, wh0, hp[pp * 2]);
            hp[pp * 2 + 1] = fmaf(s, wh1, hp[pp * 2 + 1]);
        }
        if (STORE_PRE) {
            *(float4*)&Cpre[j * BS + p8]     = make_float4(pre[0], pre[1], pre[2], pre[3]);
            *(float4*)&Cpre[j * BS + p8 + 4] = make_float4(pre[4], pre[5], pre[6], pre[7]);
        }
    }
    // combine head partials across h; h==0 writes the jg slot
#pragma unroll
    for (int i = 0; i < 16; i++) hp[i] += shflx8(hp[i]);
    if (h == 0) {
        float* pb = &part[jg * 128 + p8 * 2];
#pragma unroll
        for (int q = 0; q < 4; q++)
            ((float4*)pb)[q] = make_float4(hp[4 * q], hp[4 * q + 1], hp[4 * q + 2], hp[4 * q + 3]);
    }
}

// Backward GEMM + fused epilogue, j-split across partners.
// Thread (pg, h, kg): strided k-set {kg+16m}, sums j = h (mod 2); partners
// exchange so h owns m = h*4..h*4+3; corr partials -> part[kg][p][d].
__device__ __forceinline__ void gemm_bwd_epi(const float* __restrict__ Dz,
                                             const float* __restrict__ Wg,
                                             const float* __restrict__ gw1s,
                                             const float* __restrict__ gb1s,
                                             const float* __restrict__ ysm,
                                             float* __restrict__ part, int tid)
{
    const int pg = tid & 7, h = (tid >> 3) & 1, kg = tid >> 4;   // kg 0..15
    const int p8 = pg * 8;
    ull acc[8][4];                              // [m][pair], k = kg + 16*m
#pragma unroll
    for (int a = 0; a < 8; a++)
#pragma unroll
        for (int c = 0; c < 4; c++) acc[a][c] = 0ULL;

#pragma unroll 4
    for (int jj = 0; jj < H / 2; jj++) {
        int j = 2 * jj + h;
        ulonglong2 a01 = *(const ulonglong2*)&Dz[j * BS + p8];
        ulonglong2 a23 = *(const ulonglong2*)&Dz[j * BS + p8 + 4];
        ull ap[4] = {a01.x, a01.y, a23.x, a23.y};
#pragma unroll
        for (int m = 0; m < 8; m++) {
            float w = Wg[(kg + 16 * m) * WS + j];
            ull wp; PACK2(wp, w, w);
#pragma unroll
            for (int q = 0; q < 4; q++)
                FMA2(acc[m][q], wp, ap[q]);
        }
    }

    // cross-h combine: owned m = h*4 + m2
    float dh1[4][8];
#pragma unroll
    for (int m2 = 0; m2 < 4; m2++) {
#pragma unroll
        for (int q = 0; q < 4; q++) {
            ull mine = h ? acc[m2 + 4][q] : acc[m2][q];
            ull othr = h ? acc[m2][q]     : acc[m2 + 4][q];
            float lo, hi;  UNPACK2(lo, hi, mine);
            float plo, phi; UNPACK2(plo, phi, othr);
            dh1[m2][2 * q]     = lo + shflx8(plo);
            dh1[m2][2 * q + 1] = hi + shflx8(phi);
        }
    }

    float w0[4], w1[4], bb[4];
#pragma unroll
    for (int m2 = 0; m2 < 4; m2++) {
        int k = kg + 16 * (h * 4 + m2);
        w0[m2] = gw1s[k];
        w1[m2] = gw1s[H + k];
        bb[m2] = gb1s[k];
    }

    float cc[16];
#pragma unroll
    for (int pp = 0; pp < 8; pp++) {
        int p = p8 + pp;
        float ya = ysm[p * 2], yb = ysm[p * 2 + 1];
        float c0 = 0.0f, c1 = 0.0f;
#pragma unroll
        for (int m2 = 0; m2 < 4; m2++) {
            float z1 = fmaf(ya, w0[m2], fmaf(yb, w1[m2], bb[m2]));
            float s  = sigmoidf_(z1);
            float spr = s * (1.0f + z1 * (1.0f - s));
            float dz1 = dh1[m2][pp] * spr;
            c0 = fmaf(dz1, w0[m2], c0);
            c1 = fmaf(dz1, w1[m2], c1);
        }
        cc[pp * 2] = c0; cc[pp * 2 + 1] = c1;
    }
#pragma unroll
    for (int i = 0; i < 16; i++) cc[i] += shflx8(cc[i]);
    if (h == 0) {
        float* pb = &part[kg * 128 + p8 * 2];
#pragma unroll
        for (int q = 0; q < 4; q++)
            ((float4*)pb)[q] = make_float4(cc[4 * q], cc[4 * q + 1], cc[4 * q + 2], cc[4 * q + 3]);
    }
}

extern "C" __global__ void __launch_bounds__(NTH, 1)
sde_milstein_kernel(const float* __restrict__ y0, const float* __restrict__ ts,
                    const float* __restrict__ dW,
                    const float* __restrict__ fw1, const float* __restrict__ fb1,
                    const float* __restrict__ fw2, const float* __restrict__ fb2,
                    const float* __restrict__ fw3, const float* __restrict__ fb3,
                    const float* __restrict__ gw1, const float* __restrict__ gb1,
                    const float* __restrict__ gw2, const float* __restrict__ gb2,
                    const float* __restrict__ gw3, const float* __restrict__ gb3,
                    float* __restrict__ out, int T, int NP)
{
    extern __shared__ float sm[];
    float* fw2s = sm;                      // 17408
    float* gw2s = fw2s + H * WS;           // 17408
    float* buf1 = gw2s + H * WS;           // 8704
    float* buf2 = buf1 + H * BS;           // 8704  (z2g between G2 and P7)
    float* part = buf2 + H * BS;           // 2048
    float* fw1s = part + 16 * PPB * 2;     // 384   [i*128+k]
    float* fb1s = fw1s + 3 * H;            // 128
    float* fb2s = fb1s + H;                // 128
    float* fw3s = fb2s + H;                // 256   [j*2+d]
    float* fb3s = fw3s + H * 2;            // 4
    float* gw1s = fb3s + 4;                // 256   [i*128+k]
    float* gb1s = gw1s + 2 * H;            // 128
    float* gb2s = gb1s + H;                // 128
    float* gw3s = gb2s + H;                // 256   [j*2+d]
    float* gb3s = gw3s + H * 2;            // 4
    float* ysm  = gb3s + 4;                // 128   [p*2+d]
    float* f_sm = ysm + PPB * 2;           // 128
    float* g_sm = f_sm + PPB * 2;          // 128
    float* dw_sm = g_sm + PPB * 2;         // 128
    float* dr_sm = dw_sm + PPB * 2;        // 128

    const int tid = threadIdx.x;
    const int p0g = blockIdx.x * PPB;

    // ---- load weights into shared ----
    for (int i = tid; i < H * H; i += NTH) {
        int k = i >> 7, j = i & 127;
        fw2s[k * WS + j] = fw2[i];
        gw2s[k * WS + j] = gw2[i];
    }
    for (int i = tid; i < 3 * H; i += NTH) fw1s[i] = fw1[i];
    for (int i = tid; i < 2 * H; i += NTH) {
        gw1s[i] = gw1[i];
        fw3s[i] = fw3[i];
        gw3s[i] = gw3[i];
    }
    for (int i = tid; i < H; i += NTH) {
        fb1s[i] = fb1[i]; fb2s[i] = fb2[i];
        gb1s[i] = gb1[i]; gb2s[i] = gb2[i];
    }
    if (tid < 2) { fb3s[tid] = fb3[tid]; gb3s[tid] = gb3[tid]; }

    // ---- init state + write t=0 output ----
    if (tid < 2 * PPB) {
        int p = tid >> 1, d = tid & 1;
        float v = y0[(size_t)(p0g) * 2 + tid];
        ysm[tid] = v;
        out[(size_t)(p0g + p) * (size_t)(T * 2) + d] = v;
    }
    __syncthreads();

    const int pA = tid & 63;     // path for elementwise-over-k phases
    const int kA = tid >> 6;     // starting k (0..3), step 4

    for (int t = 0; t < T - 1; ++t) {
        float dt = ts[t + 1] - ts[t];
        float sqdt = sqrtf(dt);

        // P1: drift layer1 -> buf1 = silu([y, spread] @ fw1 + fb1), transposed [k][p]
        {
            float ya = ysm[pA * 2], yb = ysm[pA * 2 + 1], yc = ya - yb;
#pragma unroll 4
            for (int k = kA; k < H; k += 4) {
                float z = fb1s[k];
                z = fmaf(ya, fw1s[k], z);
                z = fmaf(yb, fw1s[H + k], z);
                z = fmaf(yc, fw1s[2 * H + k], z);
                buf1[k * BS + pA] = siluf_(z);
            }
        }
        __syncthreads();

        // G1: drift L2 + fused f-head -> part
        gemm_head<false>(buf1, fw2s, fb2s, fw3s, (float*)0, part, tid);
        __syncthreads();

        // P4: f-reduce (tid<128) + diffusion layer1 -> buf1 (all threads)
        {
            if (tid < 128) {
                float a = 0.0f;
#pragma unroll
                for (int jg2 = 0; jg2 < 16; jg2++) a += part[jg2 * 128 + tid];
                f_sm[tid] = a + fb3s[tid & 1];
            }
            float ya = ysm[pA * 2], yb = ysm[pA * 2 + 1];
#pragma unroll 4
            for (int k = kA; k < H; k += 4) {
                float z = fmaf(ya, gw1s[k], fmaf(yb, gw1s[H + k], gb1s[k]));
                buf1[k * BS + pA] = siluf_(z);
            }
        }
        __syncthreads();

        // G2: diffusion L2 -> buf2 (pre-act z2g) + fused raw-head -> part
        gemm_head<true>(buf1, gw2s, gb2s, gw3s, buf2, part, tid);
        __syncthreads();

        // P6: reduce raw; g = clip(softplus(raw)); Milstein cotangent draw
        if (tid < 128) {
            int p = tid >> 1, d = tid & 1;
            float raw = gb3s[d];
#pragma unroll
            for (int jg2 = 0; jg2 < 16; jg2++) raw += part[jg2 * 128 + tid];
            float e  = __expf(raw);
            float sp = (raw > 15.0f) ? raw : log1pf(e);
            float g  = fminf(fmaxf(sp, 1e-4f), 5.0f);
            float dwv = dW[((size_t)t * (size_t)NP + (p0g + p)) * 2 + d] * sqdt;
            float v   = 0.5f * (dwv * dwv - dt);
            float sig = __fdividef(e, 1.0f + e);              // exact sigmoid(raw)
            float m   = (sp > 1e-4f && sp < 5.0f) ? 1.0f : 0.0f;
            g_sm[tid]  = g;
            dw_sm[tid] = dwv;
            dr_sm[tid] = v * g * sig * m;
        }
        __syncthreads();

        // P7: dz2 = (draw @ gw3^T) * silu'(z2g) -> buf1
        {
            float r0 = dr_sm[pA * 2], r1 = dr_sm[pA * 2 + 1];
#pragma unroll 4
            for (int k = kA; k < H; k += 4) {
                float z = buf2[k * BS + pA];
                float s = sigmoidf_(z);
                float spr = s * (1.0f + z * (1.0f - s));
                float dh2 = fmaf(r0, gw3s[k * 2], r1 * gw3s[k * 2 + 1]);
                buf1[k * BS + pA] = dh2 * spr;
            }
        }
        __syncthreads();

        // G3: dh1 = dz2 @ gw2^T, fused dz1 + corr partials -> part
        gemm_bwd_epi(buf1, gw2s, gw1s, gb1s, ysm, part, tid);
        __syncthreads();

        // P9: reduce corr, Milstein update, write output
        if (tid < 128) {
            int p = tid >> 1, d = tid & 1;
            float c = 0.0f;
#pragma unroll
            for (int kg = 0; kg < 16; kg++) c += part[kg * 128 + tid];
            float yn = ysm[tid] + f_sm[tid] * dt + g_sm[tid] * dw_sm[tid] + c;
            ysm[tid] = yn;
            out[(size_t)(p0g + p) * (size_t)(T * 2) + (size_t)(t + 1) * 2 + d] = yn;
        }
        __syncthreads();
    }
}

extern "C" void kernel_launch(void* const* d_in, const int* in_sizes, int n_in,
                              void* d_out, int out_size)
{
    const float* y0  = (const float*)d_in[0];
    const float* ts  = (const float*)d_in[1];
    const float* dW  = (const float*)d_in[2];
    const float* fw1 = (const float*)d_in[3];
    const float* fb1 = (const float*)d_in[4];
    const float* fw2 = (const float*)d_in[5];
    const float* fb2 = (const float*)d_in[6];
    const float* fw3 = (const float*)d_in[7];
    const float* fb3 = (const float*)d_in[8];
    const float* gw1 = (const float*)d_in[9];
    const float* gb1 = (const float*)d_in[10];
    const float* gw2 = (const float*)d_in[11];
    const float* gb2 = (const float*)d_in[12];
    const float* gw3 = (const float*)d_in[13];
    const float* gb3 = (const float*)d_in[14];
    float* out = (float*)d_out;

    int T  = in_sizes[1];          // 512
    int NP = in_sizes[0] / 2;      // 8192
    int nb = NP / PPB;             // 128 blocks

    cudaFuncSetAttribute(sde_milstein_kernel,
                         cudaFuncAttributeMaxDynamicSharedMemorySize, SMEM_BYTES);

    sde_milstein_kernel<<<nb, NTH, SMEM_BYTES>>>(
        y0, ts, dW, fw1, fb1, fw2, fb2, fw3, fb3,
        gw1, gb1, gw2, gb2, gw3, gb3, out, T, NP);
}